// round 6
// baseline (speedup 1.0000x reference)
#include <cuda_runtime.h>
#include <cuda_bf16.h>

// PositionalEmbedding: out[l, :] = emb_table[token_ids[l], :] + PE(l, :)
// PE pairs p in [0,255): col 2p = sin(l / 10000^(2p/512)), col 2p+1 = cos(...).
// Cols 510, 511 get PE = 0 (reference only fills 255 pairs).

#define SEQ   131072
#define DEPTH 512
#define ROWS_PER_GROUP 4   // rows per 64-thread group (each thread: 32B/row)

// Per-pair frequency w_p = 10000^(2p/512), correctly-rounded fp32 (computed in
// double so it matches the reference's fp32 frequency bit-for-bit).
__device__ float g_w[256];

__global__ void setup_freq_kernel() {
    int p = threadIdx.x;
    if (p < 255) {
        double y = (double)(2 * p) / 512.0;          // exact in double
        double w = exp(y * 9.210340371976184);       // ln(10000)
        g_w[p] = (float)w;
    } else if (p == 255) {
        g_w[p] = 1.0f;  // unused (guarded)
    }
}

// 256-bit table gather with L2 evict-last (sm_103 requires .v8.b32 width for
// the evict_last modifier). Gathered rows are the reused working set (103MB
// table vs 126MB L2, avg 2.6x reuse/row); keep them resident while the 256MB
// output stream (evict-first stores) passes through.
__device__ __forceinline__ void ldg_el_256(const float* p, float* v) {
    asm("ld.global.nc.L2::evict_last.v8.b32 {%0,%1,%2,%3,%4,%5,%6,%7}, [%8];"
        : "=f"(v[0]), "=f"(v[1]), "=f"(v[2]), "=f"(v[3]),
          "=f"(v[4]), "=f"(v[5]), "=f"(v[6]), "=f"(v[7])
        : "l"(p));
}

// Accurate sin/cos of the fp32-rounded angle a = fl32(fi / w), mimicking
// jnp.sin/jnp.cos applied to the reference's fp32 angle.
//  - __fdiv_rn: IEEE round-to-nearest division (matches reference's angle bits)
//  - two-word Cody-Waite reduction mod 2pi (k <= 20861 for a <= 131071)
//  - MUFU sin/cos on the reduced argument |r| <= pi + 0.01
__device__ __forceinline__ float2 pe_pair(float fi, float w) {
    float a = __fdiv_rn(fi, w);
    float k = rintf(a * 0.15915494309189535f);
    // 2pi = HI + MID; HI = fl32(2pi), MID = 2pi - HI = -1.7484555e-7
    float r = fmaf(k, -6.283185307179586f, a);   // literal rounds to HI
    r = fmaf(k, 1.7484556e-07f, r);              // add back k*(HI - 2pi)
    float s, c;
    __sincosf(r, &s, &c);
    return make_float2(s, c);
}

__global__ void __launch_bounds__(256) emb_pe_kernel(
    const int*   __restrict__ tok,
    const float* __restrict__ tab,
    float*       __restrict__ out)
{
    const int tid  = threadIdx.x;
    const int t    = tid & 63;                   // 32B-chunk index within a row
    const int grp  = tid >> 6;                   // 0..3
    const int base = (blockIdx.x * 4 + grp) * ROWS_PER_GROUP;

    // ---- 4 token ids via one coalesced int4 load (broadcast in group) ----
    const int4 tk4 = __ldg(reinterpret_cast<const int4*>(tok + base));
    const int tk[ROWS_PER_GROUP] = {tk4.x, tk4.y, tk4.z, tk4.w};

    // ---- front-batched independent 32B table gathers (evict-last) ----
    float e[ROWS_PER_GROUP][8];
#pragma unroll
    for (int r = 0; r < ROWS_PER_GROUP; r++)
        ldg_el_256(tab + ((size_t)tk[r] << 9) + (t << 3), e[r]);

    // frequencies for pairs 4t .. 4t+3 — coalesced float4 load
    const float4 w    = __ldg(reinterpret_cast<const float4*>(g_w) + t);
    const bool   tail = (t == 63);               // pair 255 -> PE = 0

#pragma unroll
    for (int r = 0; r < ROWS_PER_GROUP; r++) {
        const float fi = (float)(base + r);
        float o[8];
        {
            float2 sc = pe_pair(fi, w.x);        // pair 4t
            o[0] = e[r][0] + sc.x;  o[1] = e[r][1] + sc.y;
        }
        {
            float2 sc = pe_pair(fi, w.y);        // pair 4t+1
            o[2] = e[r][2] + sc.x;  o[3] = e[r][3] + sc.y;
        }
        {
            float2 sc = pe_pair(fi, w.z);        // pair 4t+2
            o[4] = e[r][4] + sc.x;  o[5] = e[r][5] + sc.y;
        }
        if (!tail) {
            float2 sc = pe_pair(fi, w.w);        // pair 4t+3
            o[6] = e[r][6] + sc.x;  o[7] = e[r][7] + sc.y;
        } else {
            o[6] = e[r][6];  o[7] = e[r][7];
        }
        // Streaming stores: keep the output stream from evicting the table.
        float4* op = reinterpret_cast<float4*>(out) + ((size_t)(base + r) << 7) + (t << 1);
        __stcs(op,     make_float4(o[0], o[1], o[2], o[3]));
        __stcs(op + 1, make_float4(o[4], o[5], o[6], o[7]));
    }
}

extern "C" void kernel_launch(void* const* d_in, const int* in_sizes, int n_in,
                              void* d_out, int out_size) {
    const int*   tok = (const int*)d_in[0];     // token_ids, int32 [131072]
    const float* tab = (const float*)d_in[1];   // emb_table, fp32 [50257, 512]
    float*       out = (float*)d_out;           // fp32 [131072, 512]

    setup_freq_kernel<<<1, 256>>>();
    emb_pe_kernel<<<SEQ / (4 * ROWS_PER_GROUP), 256>>>(tok, tab, out);
}